// round 6
// baseline (speedup 1.0000x reference)
#include <cuda_runtime.h>

// Problem constants (fixed by the reference).
#define BATCH 512
#define LSEQ  24576
#define LP    8192        // LSEQ / 3
#define HID   10

// Scratch for conv output (16 MB + pad for the 8-step prefetch overread).
__device__ float g_conv[(size_t)BATCH * LP + 8];

// ---------------------------------------------------------------------------
// Kernel 1: conv1d k=3 stride=3 + bias + relu.
// ---------------------------------------------------------------------------
__global__ void conv_kernel(const float* __restrict__ x,
                            const float* __restrict__ cw,
                            const float* __restrict__ cb) {
    int idx = blockIdx.x * blockDim.x + threadIdx.x;   // 0 .. 512*2048-1
    int b = idx >> 11;          // 2048 quads per batch row
    int i = idx & 2047;
    if (b >= BATCH) return;

    const float4* xp = reinterpret_cast<const float4*>(x + (size_t)b * LSEQ + 12 * i);
    float4 a = xp[0];
    float4 m = xp[1];
    float4 c = xp[2];

    float w0 = cw[0], w1 = cw[1], w2 = cw[2], b0 = cb[0];

    float o0 = fmaf(a.x, w0, fmaf(a.y, w1, fmaf(a.z, w2, b0)));
    float o1 = fmaf(a.w, w0, fmaf(m.x, w1, fmaf(m.y, w2, b0)));
    float o2 = fmaf(m.z, w0, fmaf(m.w, w1, fmaf(c.x, w2, b0)));
    float o3 = fmaf(c.y, w0, fmaf(c.z, w1, fmaf(c.w, w2, b0)));

    float4 o;
    o.x = fmaxf(o0, 0.0f);
    o.y = fmaxf(o1, 0.0f);
    o.z = fmaxf(o2, 0.0f);
    o.w = fmaxf(o3, 0.0f);
    *reinterpret_cast<float4*>(g_conv + (size_t)b * LP + 4 * i) = o;
}

// ---------------------------------------------------------------------------
// Packed f32x2 + MUFU helpers.
// ---------------------------------------------------------------------------
typedef unsigned long long u64;

__device__ __forceinline__ u64 dup2(float x) {
    u64 r;
    asm("mov.b64 %0, {%1, %1};" : "=l"(r) : "f"(x));
    return r;
}
__device__ __forceinline__ u64 pack2(float lo, float hi) {
    u64 r;
    asm("mov.b64 %0, {%1, %2};" : "=l"(r) : "f"(lo), "f"(hi));
    return r;
}
__device__ __forceinline__ u64 ffma2(u64 a, u64 b, u64 c) {
    u64 d;
    asm("fma.rn.f32x2 %0, %1, %2, %3;" : "=l"(d) : "l"(a), "l"(b), "l"(c));
    return d;
}
__device__ __forceinline__ u64 mul2(u64 a, u64 b) {
    u64 d;
    asm("mul.rn.f32x2 %0, %1, %2;" : "=l"(d) : "l"(a), "l"(b));
    return d;
}
__device__ __forceinline__ u64 add2f(u64 a, u64 b) {
    u64 d;
    asm("add.rn.f32x2 %0, %1, %2;" : "=l"(d) : "l"(a), "l"(b));
    return d;
}
__device__ __forceinline__ float hsum2(u64 v) {
    float lo, hi;
    asm("mov.b64 {%0, %1}, %2;" : "=f"(lo), "=f"(hi) : "l"(v));
    return lo + hi;
}
__device__ __forceinline__ float tanh_apx(float x) {
    float y;
    asm("tanh.approx.f32 %0, %1;" : "=f"(y) : "f"(x));
    return y;
}

// Shared-memory broadcast helpers: h vector read back as packed 64-bit pairs.
__device__ __forceinline__ void sts_f32(unsigned addr, float v) {
    asm volatile("st.shared.f32 [%0], %1;" :: "r"(addr), "f"(v) : "memory");
}
__device__ __forceinline__ void lds_v2u64(unsigned addr, u64& a, u64& b) {
    asm volatile("ld.shared.v2.u64 {%0,%1}, [%2];"
                 : "=l"(a), "=l"(b) : "r"(addr) : "memory");
}
__device__ __forceinline__ u64 lds_u64(unsigned addr) {
    u64 a;
    asm volatile("ld.shared.u64 %0, [%1];" : "=l"(a) : "r"(addr) : "memory");
    return a;
}
__device__ __forceinline__ void lds_v2f(unsigned addr, float& a, float& b) {
    asm volatile("ld.shared.v2.f32 {%0,%1}, [%2];"
                 : "=f"(a), "=f"(b) : "r"(addr) : "memory");
}

// ---------------------------------------------------------------------------
// Kernel 2: LSTM scan + final MLP.
// Lane j<10 of a 16-lane segment owns hidden unit j. Gate dots via FFMA2 over
// k-pairs in TWO parallel chains (depth 2 and 3) combined with add2 -> preact
// ready at h+20 instead of h+24. 8-step unroll to bury loop overhead.
// ---------------------------------------------------------------------------
__global__ void __launch_bounds__(128, 1)
lstm_kernel(const float* __restrict__ w_ih,
            const float* __restrict__ w_hh,
            const float* __restrict__ b_ih,
            const float* __restrict__ b_hh,
            const float* __restrict__ mlp_w,
            const float* __restrict__ mlp_b,
            float* __restrict__ out) {
    __shared__ __align__(16) float hbuf[8 * 16];   // 8 segments * 16 slots

    int tid = blockIdx.x * blockDim.x + threadIdx.x;
    int grp = tid >> 4;                 // batch element, 0..511
    int j   = tid & 15;                 // lane within segment
    int jc  = j < HID ? j : HID - 1;    // clamp idle lanes onto valid rows
    if (grp >= BATCH) return;

    int seg = (threadIdx.x >> 4);       // segment within block, 0..7
    unsigned sbase = (unsigned)__cvta_generic_to_shared(&hbuf[seg * 16]);
    unsigned smy   = sbase + 4u * (unsigned)j;

    // Recurrent weights packed over k-pairs (torch gate order i,f,g,o).
    // Sigmoid-gate weights pre-scaled by 0.5 (sigmoid via tanh identity).
    u64 wi2[5], wf2[5], wg2[5], wo2[5];
#pragma unroll
    for (int p = 0; p < 5; p++) {
        wi2[p] = pack2(0.5f * w_hh[(0 * HID + jc) * HID + 2 * p],
                       0.5f * w_hh[(0 * HID + jc) * HID + 2 * p + 1]);
        wf2[p] = pack2(0.5f * w_hh[(1 * HID + jc) * HID + 2 * p],
                       0.5f * w_hh[(1 * HID + jc) * HID + 2 * p + 1]);
        wg2[p] = pack2(       w_hh[(2 * HID + jc) * HID + 2 * p],
                              w_hh[(2 * HID + jc) * HID + 2 * p + 1]);
        wo2[p] = pack2(0.5f * w_hh[(3 * HID + jc) * HID + 2 * p],
                       0.5f * w_hh[(3 * HID + jc) * HID + 2 * p + 1]);
    }
    // Input weight + bias packed into (value, 0): seeded via one FFMA2 each.
    u64 wxi2 = pack2(0.5f * w_ih[0 * HID + jc], 0.0f);
    u64 wxf2 = pack2(0.5f * w_ih[1 * HID + jc], 0.0f);
    u64 wxg2 = pack2(       w_ih[2 * HID + jc], 0.0f);
    u64 wxo2 = pack2(0.5f * w_ih[3 * HID + jc], 0.0f);
    u64 bbi2 = pack2(0.5f * (b_ih[0 * HID + jc] + b_hh[0 * HID + jc]), 0.0f);
    u64 bbf2 = pack2(0.5f * (b_ih[1 * HID + jc] + b_hh[1 * HID + jc]), 0.0f);
    u64 bbg2 = pack2(       (b_ih[2 * HID + jc] + b_hh[2 * HID + jc]), 0.0f);
    u64 bbo2 = pack2(0.5f * (b_ih[3 * HID + jc] + b_hh[3 * HID + jc]), 0.0f);

    float cst = 0.0f;
    float hcst = 0.0f;                  // 0.5 * cst, maintained each step

    // Seed h = 0 in smem.
    sts_f32(smy, 0.0f);

    const float* convp = g_conv + (size_t)grp * LP;
    float4 cur0 = *reinterpret_cast<const float4*>(convp);
    float4 cur1 = *reinterpret_cast<const float4*>(convp + 4);

    for (int t8 = 0; t8 < LP / 8; t8++) {
        // Prefetch next two quads (padded overread on the last iteration).
        float4 nxt0 = *reinterpret_cast<const float4*>(convp + 8 * t8 + 8);
        float4 nxt1 = *reinterpret_cast<const float4*>(convp + 8 * t8 + 12);

        float cts[8] = {cur0.x, cur0.y, cur0.z, cur0.w,
                        cur1.x, cur1.y, cur1.z, cur1.w};
#pragma unroll
        for (int u = 0; u < 8; u++) {
            u64 ct2 = dup2(cts[u]);     // off critical path (ct known early)

            // Broadcast previous h as packed pairs (smem broadcast reads).
            u64 h01, h23, h45, h67, h89;
            lds_v2u64(sbase, h01, h23);
            lds_v2u64(sbase + 16u, h45, h67);
            h89 = lds_u64(sbase + 32u);

            // Seeds (independent of h; scheduled into the LDS shadow).
            u64 sg = ffma2(wxg2, ct2, bbg2);
            u64 si = ffma2(wxi2, ct2, bbi2);
            u64 sf = ffma2(wxf2, ct2, bbf2);
            u64 so = ffma2(wxo2, ct2, bbo2);

            // Chain A (depth 2 from h): seed + h01 + h23.
            u64 gA = ffma2(wg2[0], h01, sg);
            u64 iA = ffma2(wi2[0], h01, si);
            u64 fA = ffma2(wf2[0], h01, sf);
            u64 oA = ffma2(wo2[0], h01, so);
            gA = ffma2(wg2[1], h23, gA);
            iA = ffma2(wi2[1], h23, iA);
            fA = ffma2(wf2[1], h23, fA);
            oA = ffma2(wo2[1], h23, oA);

            // Chain B (depth 3 from h): w45*h45 + h67 + h89.
            u64 gB = mul2(wg2[2], h45);
            u64 iB = mul2(wi2[2], h45);
            u64 fB = mul2(wf2[2], h45);
            u64 oB = mul2(wo2[2], h45);
            gB = ffma2(wg2[3], h67, gB);
            iB = ffma2(wi2[3], h67, iB);
            fB = ffma2(wf2[3], h67, fB);
            oB = ffma2(wo2[3], h67, oB);
            gB = ffma2(wg2[4], h89, gB);
            iB = ffma2(wi2[4], h89, iB);
            fB = ffma2(wf2[4], h89, fB);
            oB = ffma2(wo2[4], h89, oB);

            float ag = hsum2(add2f(gA, gB));
            float ai = hsum2(add2f(iA, iB));
            float af = hsum2(add2f(fA, fB));
            float ao = hsum2(add2f(oA, oB));

            // Activations (MUFU issue order tuned to the c-path: g, i, f, o).
            float gg = tanh_apx(ag);    // tanh gate
            float ti = tanh_apx(ai);    // tanh(0.5*preact_i)
            float tf = tanh_apx(af);
            float to = tanh_apx(ao);

            // c' = sig(f)*c + sig(i)*g with sig(x)=0.5*t+0.5 folded:
            //   P = 0.5*gg*ti + 0.5*gg ; Q = 0.5*c + P ; c' = fma(0.5*c, tf, Q)
            float hgg = 0.5f * gg;
            float P = fmaf(hgg, ti, hgg);
            float Q = hcst + P;
            cst = fmaf(hcst, tf, Q);
            hcst = 0.5f * cst;

            float og = fmaf(to, 0.5f, 0.5f);
            float h = og * tanh_apx(cst);

            // Publish new h for the next step.
            sts_f32(smy, h);
        }
        cur0 = nxt0;
        cur1 = nxt1;
    }

    // Final MLP: read h_0..h_9 from smem; lanes 0..2 emit the 3 outputs.
    if (j < 3) {
        float h0, h1, h2, h3, h4, h5, h6, h7, h8, h9;
        lds_v2f(sbase,       h0, h1);
        lds_v2f(sbase + 8u,  h2, h3);
        lds_v2f(sbase + 16u, h4, h5);
        lds_v2f(sbase + 24u, h6, h7);
        lds_v2f(sbase + 32u, h8, h9);
        const float* mw = mlp_w + j * HID;
        float acc = mlp_b[j];
        acc = fmaf(mw[0], h0, acc);
        acc = fmaf(mw[1], h1, acc);
        acc = fmaf(mw[2], h2, acc);
        acc = fmaf(mw[3], h3, acc);
        acc = fmaf(mw[4], h4, acc);
        acc = fmaf(mw[5], h5, acc);
        acc = fmaf(mw[6], h6, acc);
        acc = fmaf(mw[7], h7, acc);
        acc = fmaf(mw[8], h8, acc);
        acc = fmaf(mw[9], h9, acc);
        out[grp * 3 + j] = acc;
    }
}

// ---------------------------------------------------------------------------
extern "C" void kernel_launch(void* const* d_in, const int* in_sizes, int n_in,
                              void* d_out, int out_size) {
    const float* x      = (const float*)d_in[0];
    const float* conv_w = (const float*)d_in[1];
    const float* conv_b = (const float*)d_in[2];
    const float* w_ih   = (const float*)d_in[3];
    const float* w_hh   = (const float*)d_in[4];
    const float* b_ih   = (const float*)d_in[5];
    const float* b_hh   = (const float*)d_in[6];
    const float* mlp_w  = (const float*)d_in[7];
    const float* mlp_b  = (const float*)d_in[8];
    float* out = (float*)d_out;

    // Conv: 512*2048 threads, 4 outputs each.
    {
        int total = BATCH * (LP / 4);
        int threads = 256;
        int blocks = (total + threads - 1) / threads;
        conv_kernel<<<blocks, threads>>>(x, conv_w, conv_b);
    }
    // LSTM: 512 groups * 16 lanes = 8192 threads (64 blocks x 128).
    {
        int threads = 128;
        int blocks = (BATCH * 16) / threads;   // 64
        lstm_kernel<<<blocks, threads>>>(w_ih, w_hh, b_ih, b_hh, mlp_w, mlp_b, out);
    }
}